// round 8
// baseline (speedup 1.0000x reference)
#include <cuda_runtime.h>
#include <math.h>

#define BB   2048
#define NN   36
#define EMBD 1024
#define SIMD 16
#define HID  32
#define KK   8

__device__ __forceinline__ unsigned smem_u32(const void* p) {
    return (unsigned)__cvta_generic_to_shared(p);
}
__device__ __forceinline__ void cp_async16(unsigned dst, const void* src) {
    asm volatile("cp.async.cg.shared.global [%0], [%1], 16;" :: "r"(dst), "l"(src));
}
__device__ __forceinline__ void cp_async4(unsigned dst, const void* src) {
    asm volatile("cp.async.ca.shared.global [%0], [%1], 4;" :: "r"(dst), "l"(src));
}

__global__ __launch_bounds__(256, 5)
void simgsmn_fused(const float* __restrict__ inp1,
                   const float* __restrict__ inp2,
                   const float* __restrict__ gcn_w,
                   const float* __restrict__ out1_v,
                   const float* __restrict__ out1_g,
                   const float* __restrict__ out1_b,
                   const float* __restrict__ out2_v,
                   const float* __restrict__ out2_g,
                   const float* __restrict__ out2_b,
                   float* __restrict__ out) {
    const int b    = blockIdx.x;
    const int tid  = threadIdx.x;
    const int lane = tid & 31;
    const int warp = tid >> 5;

    __shared__ float s_gcnw[KK * SIMD * HID];   // 16 KB staged via cp.async
    __shared__ float s_vraw[HID * HID];         // 4 KB staged via cp.async
    __shared__ float s_small[96];               // out1_g | out1_b | out2_v
    __shared__ float s_b2g[2];                  // out2_g, out2_b
    __shared__ float s_sim[NN][SIMD];
    __shared__ float s_Wc[SIMD * HID];
    __shared__ float s_wsum[SIMD * HID];
    __shared__ float s_v[HID * 33];             // padded: conflict-free v[h][j]
    __shared__ float s_scale[HID];
    __shared__ float s_b1[HID];
    __shared__ float s_w2[HID];
    __shared__ float s_partial[8];

    // ---- prefetch fold inputs (non-blocking, overlaps all of phase 1) ----
    {
        #pragma unroll
        for (int m = 0; m < 4; m++)   // 1024 x 16B for gcn_w
            cp_async16(smem_u32(&s_gcnw[(tid + 256 * m) * 4]),
                       gcn_w + (tid + 256 * m) * 4);
        cp_async16(smem_u32(&s_vraw[tid * 4]), out1_v + tid * 4);  // 256 x 16B
        if (tid < 24) {
            const float* srcs[3] = { out1_g, out1_b, out2_v };
            const int a = tid >> 3, w = (tid & 7) * 4;
            cp_async16(smem_u32(&s_small[a * 32 + w]), srcs[a] + w);
        } else if (tid == 24) {
            cp_async4(smem_u32(&s_b2g[0]), out2_g);
            cp_async4(smem_u32(&s_b2g[1]), out2_b);
        }
        asm volatile("cp.async.commit_group;");
    }

    const float* p1 = inp1 + (size_t)b * (NN * EMBD);
    const float* p2 = inp2 + (size_t)b * (NN * EMBD);

    // ---- phase 1: block-wise cosine sim -> s_sim[i][d] ----
    // 64 threads per row: 16 sim-blocks x 4 threads, 8 independent LDG.128
    // per thread per iteration, 2-level butterfly. 4 rows/pass, 9 passes.
    const int rg = tid >> 6;
    const int rr = tid & 63;
    const int d  = rr >> 2;
    const int u  = rr & 3;
    const int boff = d * 64 + u * 4;

    #pragma unroll 1
    for (int p = 0; p < NN / 4; p++) {
        const int i = p * 4 + rg;
        const float4* qp = reinterpret_cast<const float4*>(p1 + i * EMBD + boff);
        const float4* cp = reinterpret_cast<const float4*>(p2 + i * EMBD + boff);

        float4 q0 = __ldcs(qp + 0);
        float4 q1 = __ldcs(qp + 4);
        float4 q2 = __ldcs(qp + 8);
        float4 q3 = __ldcs(qp + 12);
        float4 c0 = __ldcs(cp + 0);
        float4 c1 = __ldcs(cp + 4);
        float4 c2 = __ldcs(cp + 8);
        float4 c3 = __ldcs(cp + 12);

        float dqc = q0.x * c0.x + q0.y * c0.y + q0.z * c0.z + q0.w * c0.w
                  + q1.x * c1.x + q1.y * c1.y + q1.z * c1.z + q1.w * c1.w
                  + q2.x * c2.x + q2.y * c2.y + q2.z * c2.z + q2.w * c2.w
                  + q3.x * c3.x + q3.y * c3.y + q3.z * c3.z + q3.w * c3.w;
        float nq  = q0.x * q0.x + q0.y * q0.y + q0.z * q0.z + q0.w * q0.w
                  + q1.x * q1.x + q1.y * q1.y + q1.z * q1.z + q1.w * q1.w
                  + q2.x * q2.x + q2.y * q2.y + q2.z * q2.z + q2.w * q2.w
                  + q3.x * q3.x + q3.y * q3.y + q3.z * q3.z + q3.w * q3.w;
        float nc  = c0.x * c0.x + c0.y * c0.y + c0.z * c0.z + c0.w * c0.w
                  + c1.x * c1.x + c1.y * c1.y + c1.z * c1.z + c1.w * c1.w
                  + c2.x * c2.x + c2.y * c2.y + c2.z * c2.z + c2.w * c2.w
                  + c3.x * c3.x + c3.y * c3.y + c3.z * c3.z + c3.w * c3.w;

        #pragma unroll
        for (int o = 2; o > 0; o >>= 1) {
            dqc += __shfl_xor_sync(0xFFFFFFFFu, dqc, o);
            nq  += __shfl_xor_sync(0xFFFFFFFFu, nq,  o);
            nc  += __shfl_xor_sync(0xFFFFFFFFu, nc,  o);
        }
        if (u == 0)
            s_sim[i][d] = dqc * rsqrtf(nq * nc);
    }
    asm volatile("cp.async.wait_group 0;");
    __syncthreads();

    // ---- fold weights from smem (prefetched; zero global stalls) ----
    {
        float ws0 = 0.f, ws1 = 0.f;
        #pragma unroll
        for (int k = 0; k < KK; k++) {
            ws0 += s_gcnw[k * (SIMD * HID) + tid];
            ws1 += s_gcnw[k * (SIMD * HID) + tid + 256];
        }
        s_wsum[tid]       = ws0;
        s_wsum[tid + 256] = ws1;

        #pragma unroll
        for (int m = 0; m < 4; m++) {
            const int e = tid + 256 * m;
            s_v[(e >> 5) * 33 + (e & 31)] = s_vraw[e];
        }
    }
    __syncthreads();

    if (tid < HID) {
        float nrm = 0.f;
        #pragma unroll
        for (int j = 0; j < HID; j++) { float v = s_v[tid * 33 + j]; nrm += v * v; }
        s_scale[tid] = s_small[tid] / (sqrtf(nrm) + 1e-12f);   // out1_g
        s_b1[tid] = s_small[32 + tid];                          // out1_b

        float n2 = 0.f;
        #pragma unroll
        for (int j = 0; j < HID; j++) { float v = s_small[64 + j]; n2 += v * v; }
        s_w2[tid] = s_b2g[0] * s_small[64 + tid] / (sqrtf(n2) + 1e-12f);  // out2
    }
    __syncthreads();

    // Wc[d][h] = scale[h] * sum_j Wsum[d][j] * v[h][j]
    #pragma unroll
    for (int m = 0; m < 2; m++) {
        const int e  = tid + 256 * m;
        const int dd = e >> 5, h = e & 31;
        float acc = 0.f;
        #pragma unroll
        for (int j = 0; j < HID; j++)
            acc += s_wsum[dd * HID + j] * s_v[h * 33 + j];
        s_Wc[e] = acc * s_scale[h];
    }
    __syncthreads();

    // ---- phase 2: per-row MLP head, warp per row ----
    float wsum = 0.f;
    for (int i = warp; i < NN; i += 8) {
        float acc = s_b1[lane];
        #pragma unroll
        for (int dd = 0; dd < SIMD; dd++)
            acc += s_sim[i][dd] * s_Wc[dd * HID + lane];
        float p = tanhf(acc) * s_w2[lane];
        #pragma unroll
        for (int o = 16; o > 0; o >>= 1)
            p += __shfl_xor_sync(0xFFFFFFFFu, p, o);
        wsum += p;
    }
    if (lane == 0) s_partial[warp] = wsum;
    __syncthreads();

    if (warp == 0) {
        float v = (lane < 8) ? s_partial[lane] : 0.f;
        #pragma unroll
        for (int o = 4; o > 0; o >>= 1)
            v += __shfl_xor_sync(0xFFFFFFFFu, v, o);
        if (lane == 0) out[b] = v * (1.0f / NN) + s_b2g[1];
    }
}

extern "C" void kernel_launch(void* const* d_in, const int* in_sizes, int n_in,
                              void* d_out, int out_size) {
    const float* inp1   = (const float*)d_in[0];
    const float* inp2   = (const float*)d_in[1];
    // d_in[2]=gk_mean, d_in[3]=gk_prec: unused — Gaussian branch collapses to
    // sum_j w_norm = S/(S+1e-8) = 1 - O(1e-7), below output tolerance.
    const float* gcn_w  = (const float*)d_in[4];
    const float* out1_v = (const float*)d_in[5];
    const float* out1_g = (const float*)d_in[6];
    const float* out1_b = (const float*)d_in[7];
    const float* out2_v = (const float*)d_in[8];
    const float* out2_g = (const float*)d_in[9];
    const float* out2_b = (const float*)d_in[10];
    float* out = (float*)d_out;

    simgsmn_fused<<<BB, 256>>>(inp1, inp2, gcn_w, out1_v, out1_g, out1_b,
                               out2_v, out2_g, out2_b, out);
}